// round 6
// baseline (speedup 1.0000x reference)
#include <cuda_runtime.h>
#include <cuda_fp16.h>
#include <cstdint>

#define B_    256
#define ATT_  196
#define RNN_  1024
#define NBIG  392

#define GT 256
#define STAGES 3
#define CLD 68

// ---- small gemm (BM=128) geometry ----
#define BM 128
#define BN 64
#define A_STAGE (BM * 128)
#define B_STAGE (BN * 128)
#define STAGE_BYTES (A_STAGE + B_STAGE)
#define GEMM_SMEM (STAGES * STAGE_BYTES)          // 73728

// ---- big gemm (BM=256) geometry ----
#define BM2 256
#define A_STAGE2 (BM2 * 128)
#define STAGE_BYTES2 (A_STAGE2 + B_STAGE)
#define GEMM_SMEM2 (STAGES * STAGE_BYTES2)        // 221184

// ---------------- fp16 arena ---------------------------------------------------
#define SZ_ATT   ((size_t)B_ * ATT_ * RNN_)
#define SZ_BV    ((size_t)B_ * RNN_)
#define SZ_WATT  ((size_t)ATT_ * RNN_)
#define SZ_WL    ((size_t)4 * RNN_ * RNN_)

#define OFF_ATT    ((size_t)0)
#define OFF_X      (OFF_ATT   + SZ_ATT)
#define OFF_PH     (OFF_X     + SZ_BV)
#define OFF_WBIG   (OFF_PH    + SZ_BV)
#define OFF_WH2A   (OFF_WBIG  + 2 * SZ_WATT)
#define OFF_WH2A1  (OFF_WH2A  + SZ_WATT)
#define OFF_WI2H   (OFF_WH2A1 + SZ_WATT)
#define OFF_WH2H   (OFF_WI2H  + SZ_WL)
#define OFF_WA2H   (OFF_WH2H  + SZ_WL)
#define OFF_ARES1  (OFF_WA2H  + SZ_WL)
#define OFF_NH     (OFF_ARES1 + SZ_BV)
#define ARENA_SZ   (OFF_NH    + SZ_BV)

__device__ __half g_h[ARENA_SZ];
__device__ __half g_V[(size_t)B_ * ATT_ * NBIG];
__device__ float  g_bbig[NBIG];
__device__ float  g_ah1[B_ * ATT_];
__device__ float  g_ah2[B_ * ATT_];
__device__ float  g_w1[B_ * ATT_];
__device__ float  g_w2[B_ * ATT_];
__device__ float  g_S[B_ * 4 * RNN_];

// ---------------- math helpers -------------------------------------------------
__device__ __forceinline__ float tanh_s(float x) {
    return 1.0f - 2.0f / (expf(2.0f * x) + 1.0f);
}
__device__ __forceinline__ float sigmoid_s(float x) {
    return 1.0f / (1.0f + expf(-x));
}
__device__ __forceinline__ uint32_t smem_u32(const void* p) {
    uint32_t a;
    asm("{ .reg .u64 t; cvta.to.shared.u64 t, %1; cvt.u32.u64 %0, t; }" : "=r"(a) : "l"(p));
    return a;
}
__device__ __forceinline__ void cp16(uint32_t dst, const void* src) {
    asm volatile("cp.async.cg.shared.global [%0], [%1], 16;" :: "r"(dst), "l"(src));
}
__device__ __forceinline__ void cp16z(uint32_t dst, const void* src, int sz) {
    asm volatile("cp.async.cg.shared.global [%0], [%1], 16, %2;" :: "r"(dst), "l"(src), "r"(sz));
}
__device__ __forceinline__ void red_add(float* p, float v) {
    asm volatile("red.global.add.f32 [%0], %1;" :: "l"(p), "f"(v) : "memory");
}

#define LDSM4(R, addr)                                                          \
    asm volatile("ldmatrix.sync.aligned.m8n8.x4.shared.b16 {%0,%1,%2,%3}, [%4];" \
        : "=r"((R)[0]), "=r"((R)[1]), "=r"((R)[2]), "=r"((R)[3]) : "r"(addr))

#define MMA16816(C, A, B0v, B1v)                                                \
    asm volatile("mma.sync.aligned.m16n8k16.row.col.f32.f16.f16.f32 "           \
        "{%0,%1,%2,%3},{%4,%5,%6,%7},{%8,%9},{%0,%1,%2,%3};"                    \
        : "+f"((C)[0]), "+f"((C)[1]), "+f"((C)[2]), "+f"((C)[3])                 \
        : "r"((A)[0]), "r"((A)[1]), "r"((A)[2]), "r"((A)[3]), "r"(B0v), "r"(B1v))

extern __shared__ uint8_t smem_raw[];

// =============================================================================
// BIG merged GEMM (single-sync multistage): job0 = V (fp16, bias bv),
// job1 = ah1 (f32, bias ba). BM2=256, BN=64, warp tile 64x32, K=1024.
// =============================================================================
__global__ __launch_bounds__(GT) void gemm_big(
    const __half* __restrict__ Av, const __half* __restrict__ Wv,
    const float* __restrict__ bv, __half* __restrict__ Vout,
    const __half* __restrict__ Aa, const __half* __restrict__ Wa,
    const float* __restrict__ ba, float* __restrict__ ah1,
    int nblk0)
{
    const int tid  = threadIdx.x;
    const int lane = tid & 31;
    const int warp = tid >> 5;
    const int wm   = warp & 3;
    const int wn   = warp >> 2;
    const int bid  = blockIdx.x;

    const bool jobV = bid < nblk0;
    const __half* A; const __half* W; int m0, n0, Ntot;
    if (jobV) { A = Av; W = Wv; n0 = (bid % 7) * BN; m0 = (bid / 7) * BM2; Ntot = NBIG; }
    else      { A = Aa; W = Wa; n0 = (bid - nblk0) * BN; m0 = 0;           Ntot = ATT_; }

    const uint32_t sbase = smem_u32(smem_raw);
    const int K = RNN_;
    const int ktotal = K / 64;   // 16

    auto load_stage = [&](int l) {
        const int s  = l % STAGES;
        const int kk = l * 64;
        const uint32_t abase = sbase + s * STAGE_BYTES2;
        const uint32_t bbase = abase + A_STAGE2;
        #pragma unroll
        for (int i = 0; i < 8; i++) {
            int q = tid + i * GT;
            int row = q >> 3, c = q & 7;
            cp16(abase + row * 128 + ((c ^ (row & 7)) << 4),
                 A + (size_t)(m0 + row) * K + kk + c * 8);
        }
        #pragma unroll
        for (int i = 0; i < 2; i++) {
            int q = tid + i * GT;
            int row = q >> 3, c = q & 7;
            int gr = n0 + row;
            const __half* src; int sz;
            if (gr < Ntot) { src = W + (size_t)gr * K + kk + c * 8; sz = 16; }
            else           { src = W;                               sz = 0;  }
            cp16z(bbase + row * 128 + ((c ^ (row & 7)) << 4), src, sz);
        }
        asm volatile("cp.async.commit_group;" ::: "memory");
    };

    float acc[4][4][4] = {};
    const int laneRow = lane & 7;
    const int m8      = (lane >> 3) & 1;
    const int cAdd    = lane >> 4;
    uint32_t aOff[4];
    #pragma unroll
    for (int f = 0; f < 4; f++)
        aOff[f] = (uint32_t)(wm * 64 + f * 16 + m8 * 8 + laneRow) * 128;
    const uint32_t bOff = (uint32_t)(wn * 32 + (lane >> 3) * 8 + laneRow) * 128;

    load_stage(0);
    load_stage(1);

    for (int kt = 0; kt < ktotal; ++kt) {
        asm volatile("cp.async.wait_group 1;" ::: "memory");
        __syncthreads();
        if (kt + 2 < ktotal) load_stage(kt + 2);
        else asm volatile("cp.async.commit_group;" ::: "memory");

        const uint32_t abase = sbase + (kt % STAGES) * STAGE_BYTES2;
        const uint32_t bbase = abase + A_STAGE2;
        #pragma unroll
        for (int ks = 0; ks < 4; ++ks) {
            uint32_t a[4][4], b0[4], b1[4];
            uint32_t aSw = (uint32_t)(((2 * ks + cAdd) ^ laneRow) << 4);
            LDSM4(b0, bbase + bOff + (uint32_t)(((2 * ks)     ^ laneRow) << 4));
            LDSM4(b1, bbase + bOff + (uint32_t)(((2 * ks + 1) ^ laneRow) << 4));
            #pragma unroll
            for (int f = 0; f < 4; f++) LDSM4(a[f], abase + aOff[f] + aSw);
            #pragma unroll
            for (int f = 0; f < 4; f++)
                #pragma unroll
                for (int j = 0; j < 4; j++)
                    MMA16816(acc[f][j], a[f], b0[j], b1[j]);
        }
    }
    __syncthreads();   // all warps done reading stages before Cst alias

    float* Cst = (float*)smem_raw;
    #pragma unroll
    for (int f = 0; f < 4; f++)
        #pragma unroll
        for (int j = 0; j < 4; j++) {
            int r0 = wm * 64 + f * 16 + (lane >> 2);
            int c0 = wn * 32 + j * 8 + (lane & 3) * 2;
            Cst[r0 * CLD + c0]           = acc[f][j][0];
            Cst[r0 * CLD + c0 + 1]       = acc[f][j][1];
            Cst[(r0 + 8) * CLD + c0]     = acc[f][j][2];
            Cst[(r0 + 8) * CLD + c0 + 1] = acc[f][j][3];
        }
    __syncthreads();

    for (int idx = tid; idx < BM2 * BN; idx += GT) {
        int r = idx >> 6, c = idx & 63, gc = n0 + c;
        if (gc < Ntot) {
            float v = Cst[r * CLD + c];
            if (jobV) Vout[(size_t)(m0 + r) * NBIG + gc] = __float2half(v + bv[gc]);
            else      ah1[(size_t)(m0 + r) * ATT_ + gc]  = v + ba[gc];
        }
    }
}

// =============================================================================
// small split-K GEMM with red.add epilogue (output pre-initialized with bias).
// z = blockIdx.z: selects K-segment matrix (kofs_per_z==0) or K-offset chunk.
// =============================================================================
__global__ __launch_bounds__(GT) void gemm_red(
    const __half* __restrict__ A0, const __half* __restrict__ A1,
    const __half* __restrict__ A2,
    const __half* __restrict__ W0, const __half* __restrict__ W1,
    const __half* __restrict__ W2,
    float* __restrict__ Cf, int ldc, int Ntot, int Kld, int Kchunk,
    int kofs_per_z)
{
    const int tid  = threadIdx.x;
    const int lane = tid & 31;
    const int warp = tid >> 5;
    const int wm   = warp & 3;
    const int wn   = warp >> 2;
    const int n0   = blockIdx.x * BN;
    const int m0   = blockIdx.y * BM;
    const int z    = blockIdx.z;

    const __half* A; const __half* W; int kofs;
    if (kofs_per_z) { A = A0; W = W0; kofs = z * kofs_per_z; }
    else {
        A = (z == 0) ? A0 : (z == 1) ? A1 : A2;
        W = (z == 0) ? W0 : (z == 1) ? W1 : W2;
        kofs = 0;
    }

    const uint32_t sbase = smem_u32(smem_raw);
    const int ktotal = Kchunk / 64;

    auto load_stage = [&](int l) {
        const int s  = l % STAGES;
        const int kk = kofs + l * 64;
        const uint32_t abase = sbase + s * STAGE_BYTES;
        const uint32_t bbase = abase + A_STAGE;
        #pragma unroll
        for (int i = 0; i < 4; i++) {
            int q = tid + i * GT;
            int row = q >> 3, c = q & 7;
            cp16(abase + row * 128 + ((c ^ (row & 7)) << 4),
                 A + (size_t)(m0 + row) * Kld + kk + c * 8);
        }
        #pragma unroll
        for (int i = 0; i < 2; i++) {
            int q = tid + i * GT;
            int row = q >> 3, c = q & 7;
            int gr = n0 + row;
            const __half* src; int sz;
            if (gr < Ntot) { src = W + (size_t)gr * Kld + kk + c * 8; sz = 16; }
            else           { src = W;                                  sz = 0;  }
            cp16z(bbase + row * 128 + ((c ^ (row & 7)) << 4), src, sz);
        }
        asm volatile("cp.async.commit_group;" ::: "memory");
    };

    float acc[2][4][4] = {};
    const int laneRow = lane & 7;
    const int m8      = (lane >> 3) & 1;
    const int cAdd    = lane >> 4;
    const uint32_t aOff0 = (uint32_t)(wm * 32 + m8 * 8 + laneRow) * 128;
    const uint32_t aOff1 = aOff0 + 16 * 128;
    const uint32_t bOff  = (uint32_t)(wn * 32 + (lane >> 3) * 8 + laneRow) * 128;

    load_stage(0);
    load_stage(1);

    for (int kt = 0; kt < ktotal; ++kt) {
        asm volatile("cp.async.wait_group 1;" ::: "memory");
        __syncthreads();
        if (kt + 2 < ktotal) load_stage(kt + 2);
        else asm volatile("cp.async.commit_group;" ::: "memory");

        const uint32_t abase = sbase + (kt % STAGES) * STAGE_BYTES;
        const uint32_t bbase = abase + A_STAGE;
        #pragma unroll
        for (int ks = 0; ks < 4; ++ks) {
            uint32_t a[2][4], b0[4], b1[4];
            uint32_t aSw = (uint32_t)(((2 * ks + cAdd) ^ laneRow) << 4);
            LDSM4(a[0], abase + aOff0 + aSw);
            LDSM4(a[1], abase + aOff1 + aSw);
            LDSM4(b0, bbase + bOff + (uint32_t)(((2 * ks)     ^ laneRow) << 4));
            LDSM4(b1, bbase + bOff + (uint32_t)(((2 * ks + 1) ^ laneRow) << 4));
            #pragma unroll
            for (int f = 0; f < 2; f++)
                #pragma unroll
                for (int j = 0; j < 4; j++)
                    MMA16816(acc[f][j], a[f], b0[j], b1[j]);
        }
    }
    __syncthreads();

    float* Cst = (float*)smem_raw;
    #pragma unroll
    for (int f = 0; f < 2; f++)
        #pragma unroll
        for (int j = 0; j < 4; j++) {
            int r0 = wm * 32 + f * 16 + (lane >> 2);
            int c0 = wn * 32 + j * 8 + (lane & 3) * 2;
            Cst[r0 * CLD + c0]           = acc[f][j][0];
            Cst[r0 * CLD + c0 + 1]       = acc[f][j][1];
            Cst[(r0 + 8) * CLD + c0]     = acc[f][j][2];
            Cst[(r0 + 8) * CLD + c0 + 1] = acc[f][j][3];
        }
    __syncthreads();

    for (int idx = tid; idx < BM * BN; idx += GT) {
        int r = idx >> 6, c = idx & 63, gc = n0 + c;
        if (gc < Ntot)
            red_add(Cf + (size_t)(m0 + r) * ldc + gc, Cst[r * CLD + c]);
    }
}

// ---------------- mega convert -------------------------------------------------
__global__ __launch_bounds__(256) void convert_all(
    const float* __restrict__ att, const float* __restrict__ x,
    const float* __restrict__ ph,
    const float* __restrict__ wa2a, const float* __restrict__ wa2a1,
    const float* __restrict__ wh2a, const float* __restrict__ wh2a1,
    const float* __restrict__ wi,   const float* __restrict__ wh,
    const float* __restrict__ wa,   __half* __restrict__ buf)
{
    const size_t e0 = SZ_ATT / 4;
    const size_t e1 = e0 + SZ_BV / 4;
    const size_t e2 = e1 + SZ_BV / 4;
    const size_t e3 = e2 + SZ_WATT / 4;
    const size_t e4 = e3 + SZ_WATT / 4;
    const size_t e5 = e4 + SZ_WATT / 4;
    const size_t e6 = e5 + SZ_WATT / 4;
    const size_t e7 = e6 + SZ_WL / 4;
    const size_t e8 = e7 + SZ_WL / 4;
    const size_t e9 = e8 + SZ_WL / 4;

    size_t i = (size_t)blockIdx.x * blockDim.x + threadIdx.x;
    if (i >= e9) return;

    const float* src; size_t rel; size_t dofs;
    if      (i < e0) { src = att;   rel = i;      dofs = OFF_ATT; }
    else if (i < e1) { src = x;     rel = i - e0; dofs = OFF_X; }
    else if (i < e2) { src = ph;    rel = i - e1; dofs = OFF_PH; }
    else if (i < e3) { src = wa2a;  rel = i - e2; dofs = OFF_WBIG; }
    else if (i < e4) { src = wa2a1; rel = i - e3; dofs = OFF_WBIG + SZ_WATT; }
    else if (i < e5) { src = wh2a;  rel = i - e4; dofs = OFF_WH2A; }
    else if (i < e6) { src = wh2a1; rel = i - e5; dofs = OFF_WH2A1; }
    else if (i < e7) { src = wi;    rel = i - e6; dofs = OFF_WI2H; }
    else if (i < e8) { src = wh;    rel = i - e7; dofs = OFF_WH2H; }
    else             { src = wa;    rel = i - e8; dofs = OFF_WA2H; }

    float4 v = ((const float4*)src)[rel];
    __half2 h0 = __floats2half2_rn(v.x, v.y);
    __half2 h1 = __floats2half2_rn(v.z, v.w);
    ((__half2*)(buf + dofs))[2 * rel]     = h0;
    ((__half2*)(buf + dofs))[2 * rel + 1] = h1;
}

// ---------------- prep: bbig, S := fused lstm bias, ah2 := bias ---------------
__global__ __launch_bounds__(256) void prep_kernel(
    const float* __restrict__ ba,  const float* __restrict__ ba1,
    const float* __restrict__ bi,  const float* __restrict__ bh,
    const float* __restrict__ bg,  const float* __restrict__ bh2a1,
    float* __restrict__ bbig, float* __restrict__ S, float* __restrict__ ah2)
{
    size_t i = (size_t)blockIdx.x * blockDim.x + threadIdx.x;
    if (i < NBIG) bbig[i] = (i < ATT_) ? ba[i] : ba1[i - ATT_];
    if (i < (size_t)B_ * ATT_) {
        int a = (int)(i - (i / ATT_) * ATT_);
        ah2[i] = bh2a1[a];
    }
    if (i < (size_t)B_ * 4 * RNN_) {
        int j = (int)(i & (4 * RNN_ - 1));
        S[i] = bi[j] + bh[j] + bg[j];
    }
}

// ---------------- fused reduce_dot + softmax (one CTA per batch) --------------
__global__ __launch_bounds__(256) void rds_kernel(
    const __half* __restrict__ V, int colofs, const float* __restrict__ ah,
    const float* __restrict__ Wd, const float* __restrict__ bd,
    float* __restrict__ w)
{
    int b = blockIdx.x, t = threadIdx.x, warp = t >> 5, lane = t & 31;
    __shared__ float wds[ATT_];
    __shared__ float sd[256];
    __shared__ float red[256];
    for (int j = t; j < ATT_; j += 256) wds[j] = Wd[j];
    if (t >= ATT_) sd[t] = -1e30f;
    __syncthreads();

    float bd0 = bd[0];
    for (int a = warp; a < ATT_; a += 8) {
        int m = b * ATT_ + a;
        const __half* vr = V + (size_t)m * NBIG + colofs;
        float ahm = ah[m];
        float s = 0.f;
        #pragma unroll 2
        for (int j = lane; j < ATT_; j += 32)
            s += wds[j] * tanh_s(__half2float(vr[j]) + ahm);
        #pragma unroll
        for (int o = 16; o; o >>= 1) s += __shfl_down_sync(0xffffffffu, s, o);
        if (lane == 0) sd[a] = s + bd0;
    }
    __syncthreads();

    float v = sd[t];
    red[t] = v; __syncthreads();
    #pragma unroll
    for (int s = 128; s; s >>= 1) { if (t < s) red[t] = fmaxf(red[t], red[t + s]); __syncthreads(); }
    float mx = red[0]; __syncthreads();
    float e = (t < ATT_) ? expf(v - mx) : 0.f;
    red[t] = e; __syncthreads();
    #pragma unroll
    for (int s = 128; s; s >>= 1) { if (t < s) red[t] += red[t + s]; __syncthreads(); }
    float inv = 1.0f / red[0];
    if (t < ATT_) w[b * ATT_ + t] = e * inv;
}

// ---------------- attres --------------------------------------------------------
__global__ __launch_bounds__(128) void attres_kernel(
    const __half* __restrict__ attH, const float* __restrict__ w,
    const float* __restrict__ addend, float* __restrict__ outF,
    __half* __restrict__ outH)
{
    int b = blockIdx.x;
    int t = threadIdx.x;
    __shared__ float ws[ATT_];
    for (int a = t; a < ATT_; a += 128) ws[a] = w[b * ATT_ + a];
    __syncthreads();
    int col = t * 8;
    const uint4* base = (const uint4*)(attH + (size_t)b * ATT_ * RNN_ + col);
    float s[8] = {};
    #pragma unroll 4
    for (int a = 0; a < ATT_; ++a) {
        uint4 u = base[(size_t)a * (RNN_ / 8)];
        const __half2* hp = (const __half2*)&u;
        float wa = ws[a];
        #pragma unroll
        for (int q = 0; q < 4; q++) {
            float2 f = __half22float2(hp[q]);
            s[2 * q]     += wa * f.x;
            s[2 * q + 1] += wa * f.y;
        }
    }
    if (addend) {
        #pragma unroll
        for (int q = 0; q < 8; q++) s[q] += addend[(size_t)b * RNN_ + col + q];
    }
    if (outF) {
        #pragma unroll
        for (int q = 0; q < 8; q += 4)
            *(float4*)(outF + (size_t)b * RNN_ + col + q) =
                make_float4(s[q], s[q + 1], s[q + 2], s[q + 3]);
    }
    if (outH) {
        __half2 h[4];
        #pragma unroll
        for (int q = 0; q < 4; q++) h[q] = __floats2half2_rn(s[2 * q], s[2 * q + 1]);
        *(uint4*)(outH + (size_t)b * RNN_ + col) = *(uint4*)h;
    }
}

// ---------------- LSTM gates ----------------------------------------------------
__global__ __launch_bounds__(256) void gates_kernel(
    const float* __restrict__ S, const float* __restrict__ prev_c,
    float* __restrict__ next_c, float* __restrict__ next_h,
    __half* __restrict__ nhH)
{
    int i = blockIdx.x * blockDim.x + threadIdx.x;
    int b = i >> 10, n = i & 1023;
    const float* s = S + (size_t)b * 4 * RNN_;
    float si = s[n];
    float sf = s[RNN_ + n];
    float so = s[2 * RNN_ + n];
    float st = s[3 * RNN_ + n];
    float c = sigmoid_s(sf) * prev_c[i] + sigmoid_s(si) * tanh_s(st);
    float h = sigmoid_s(so) * tanh_s(c);
    next_c[i] = c;
    next_h[i] = h;
    nhH[i]    = __float2half(h);
}

// ---------------- launcher ------------------------------------------------------
extern "C" void kernel_launch(void* const* d_in, const int* in_sizes, int n_in,
                              void* d_out, int out_size)
{
    const float* x      = (const float*)d_in[0];
    const float* att    = (const float*)d_in[1];
    const float* prev_h = (const float*)d_in[2];
    const float* prev_c = (const float*)d_in[3];
    const float* W_a2a  = (const float*)d_in[4];
    const float* b_a2a  = (const float*)d_in[5];
    const float* W_h2a  = (const float*)d_in[6];
    const float* b_h2a  = (const float*)d_in[7];
    const float* W_d2d  = (const float*)d_in[8];
    const float* b_d2d  = (const float*)d_in[9];
    const float* W_a2h  = (const float*)d_in[10];
    const float* b_a2h  = (const float*)d_in[11];
    const float* W_i2h  = (const float*)d_in[12];
    const float* b_i2h  = (const float*)d_in[13];
    const float* W_h2h  = (const float*)d_in[14];
    const float* b_h2h  = (const float*)d_in[15];
    const float* W_a2a1 = (const float*)d_in[16];
    const float* b_a2a1 = (const float*)d_in[17];
    const float* W_h2a1 = (const float*)d_in[18];
    const float* b_h2a1 = (const float*)d_in[19];
    const float* W_d2d1 = (const float*)d_in[20];
    const float* b_d2d1 = (const float*)d_in[21];

    float* out    = (float*)d_out;
    float* next_c = out;
    float* next_h = out + (size_t)B_ * RNN_;
    float* top_h  = out + (size_t)2 * B_ * RNN_;

    __half* H; __half* V;
    float *bbig, *ah1, *ah2, *w1, *w2, *S;
    cudaGetSymbolAddress((void**)&H,    g_h);
    cudaGetSymbolAddress((void**)&V,    g_V);
    cudaGetSymbolAddress((void**)&bbig, g_bbig);
    cudaGetSymbolAddress((void**)&ah1,  g_ah1);
    cudaGetSymbolAddress((void**)&ah2,  g_ah2);
    cudaGetSymbolAddress((void**)&w1,   g_w1);
    cudaGetSymbolAddress((void**)&w2,   g_w2);
    cudaGetSymbolAddress((void**)&S,    g_S);

    cudaFuncSetAttribute(gemm_red, cudaFuncAttributeMaxDynamicSharedMemorySize, GEMM_SMEM);
    cudaFuncSetAttribute(gemm_big, cudaFuncAttributeMaxDynamicSharedMemorySize, GEMM_SMEM2);

    const int Mbig = B_ * ATT_;                 // 50176
    const int NBLK0 = 7 * (Mbig / BM2);         // 1372
    const size_t CV_TOT = OFF_ARES1 / 4;

    // 1) prep (biases + S/ah2 init)
    prep_kernel<<<(unsigned)((B_ * 4 * RNN_ + 255) / 256), 256>>>(
        b_a2a, b_a2a1, b_i2h, b_h2h, b_a2h, b_h2a1, bbig, S, ah2);

    // 2) convert all f32 -> fp16 arena
    convert_all<<<(unsigned)((CV_TOT + 255) / 256), 256>>>(
        att, x, prev_h, W_a2a, W_a2a1, W_h2a, W_h2a1, W_i2h, W_h2h, W_a2h, H);

    // 3) merged: V = attH @ [Wa2a|Wa2a1]^T  +  ah1 = prev_h @ W_h2a^T
    gemm_big<<<NBLK0 + 4, GT, GEMM_SMEM2>>>(
        H + OFF_ATT, H + OFF_WBIG, bbig, V,
        H + OFF_PH,  H + OFF_WH2A, b_h2a, ah1, NBLK0);

    // 4) attend 1
    rds_kernel<<<B_, 256>>>(V, 0, ah1, W_d2d, b_d2d, w1);
    attres_kernel<<<B_, 128>>>(H + OFF_ATT, w1, nullptr, nullptr, H + OFF_ARES1);

    // 5) LSTM: S += xH@Wi^T + phH@Wh^T + ares1H@Wa^T  (3-way split-K red.add)
    gemm_red<<<dim3(64, 2, 3), GT, GEMM_SMEM>>>(
        H + OFF_X, H + OFF_PH, H + OFF_ARES1,
        H + OFF_WI2H, H + OFF_WH2H, H + OFF_WA2H,
        S, 4 * RNN_, 4 * RNN_, RNN_, RNN_, 0);

    gates_kernel<<<(B_ * RNN_) / 256, 256>>>(S, prev_c, next_c, next_h, H + OFF_NH);

    // 6) ah2 += next_h @ W_h2a1^T  (4-way split-K red.add)
    gemm_red<<<dim3(4, 2, 4), GT, GEMM_SMEM>>>(
        H + OFF_NH, nullptr, nullptr, H + OFF_WH2A1, nullptr, nullptr,
        ah2, ATT_, ATT_, RNN_, RNN_ / 4, RNN_ / 4);

    // 7) attend 2
    rds_kernel<<<B_, 256>>>(V, ATT_, ah2, W_d2d1, b_d2d1, w2);
    attres_kernel<<<B_, 128>>>(H + OFF_ATT, w2, next_h, top_h, nullptr);
}

// round 7
// speedup vs baseline: 1.2386x; 1.2386x over previous
#include <cuda_runtime.h>
#include <cuda_fp16.h>
#include <cstdint>

#define B_    256
#define ATT_  196
#define RNN_  1024
#define NBIG  392

#define GT 256
#define STAGES 3
#define CLD 68

// ---- small gemm (BM=128) geometry ----
#define BM 128
#define BN 64
#define A_STAGE (BM * 128)
#define B_STAGE (BN * 128)
#define STAGE_BYTES (A_STAGE + B_STAGE)
#define GEMM_SMEM (STAGES * STAGE_BYTES)          // 73728

// ---- big gemm (BM=256) geometry ----
#define BM2 256
#define A_STAGE2 (BM2 * 128)
#define STAGE_BYTES2 (A_STAGE2 + B_STAGE)
#define GEMM_SMEM2 (STAGES * STAGE_BYTES2)        // 122880

// ---------------- fp16 arena ---------------------------------------------------
#define SZ_ATT   ((size_t)B_ * ATT_ * RNN_)
#define SZ_BV    ((size_t)B_ * RNN_)
#define SZ_WATT  ((size_t)ATT_ * RNN_)
#define SZ_WL    ((size_t)4 * RNN_ * RNN_)

#define OFF_ATT    ((size_t)0)
#define OFF_X      (OFF_ATT   + SZ_ATT)
#define OFF_PH     (OFF_X     + SZ_BV)
#define OFF_WBIG   (OFF_PH    + SZ_BV)
#define OFF_WH2A   (OFF_WBIG  + 2 * SZ_WATT)
#define OFF_WH2A1  (OFF_WH2A  + SZ_WATT)
#define OFF_WI2H   (OFF_WH2A1 + SZ_WATT)
#define OFF_WH2H   (OFF_WI2H  + SZ_WL)
#define OFF_WA2H   (OFF_WH2H  + SZ_WL)
#define OFF_ARES1  (OFF_WA2H  + SZ_WL)
#define OFF_NH     (OFF_ARES1 + SZ_BV)
#define ARENA_SZ   (OFF_NH    + SZ_BV)

__device__ __half g_h[ARENA_SZ];
__device__ __half g_V[(size_t)B_ * ATT_ * NBIG];
__device__ float  g_bbig[NBIG];
__device__ float  g_ah1[B_ * ATT_];
__device__ float  g_ah2[B_ * ATT_];
__device__ float  g_dot[B_ * ATT_];
__device__ float  g_w1[B_ * ATT_];
__device__ float  g_w2[B_ * ATT_];
__device__ float  g_S[B_ * 4 * RNN_];

// ---------------- math helpers -------------------------------------------------
__device__ __forceinline__ float tanh_s(float x) {
    return 1.0f - 2.0f / (expf(2.0f * x) + 1.0f);
}
__device__ __forceinline__ float sigmoid_s(float x) {
    return 1.0f / (1.0f + expf(-x));
}
__device__ __forceinline__ uint32_t smem_u32(const void* p) {
    uint32_t a;
    asm("{ .reg .u64 t; cvta.to.shared.u64 t, %1; cvt.u32.u64 %0, t; }" : "=r"(a) : "l"(p));
    return a;
}
__device__ __forceinline__ void cp16(uint32_t dst, const void* src) {
    asm volatile("cp.async.cg.shared.global [%0], [%1], 16;" :: "r"(dst), "l"(src));
}
__device__ __forceinline__ void cp16z(uint32_t dst, const void* src, int sz) {
    asm volatile("cp.async.cg.shared.global [%0], [%1], 16, %2;" :: "r"(dst), "l"(src), "r"(sz));
}
__device__ __forceinline__ void red_add(float* p, float v) {
    asm volatile("red.global.add.f32 [%0], %1;" :: "l"(p), "f"(v) : "memory");
}

#define LDSM4(R, addr)                                                          \
    asm volatile("ldmatrix.sync.aligned.m8n8.x4.shared.b16 {%0,%1,%2,%3}, [%4];" \
        : "=r"((R)[0]), "=r"((R)[1]), "=r"((R)[2]), "=r"((R)[3]) : "r"(addr))

#define MMA16816(C, A, B0v, B1v)                                                \
    asm volatile("mma.sync.aligned.m16n8k16.row.col.f32.f16.f16.f32 "           \
        "{%0,%1,%2,%3},{%4,%5,%6,%7},{%8,%9},{%0,%1,%2,%3};"                    \
        : "+f"((C)[0]), "+f"((C)[1]), "+f"((C)[2]), "+f"((C)[3])                 \
        : "r"((A)[0]), "r"((A)[1]), "r"((A)[2]), "r"((A)[3]), "r"(B0v), "r"(B1v))

extern __shared__ uint8_t smem_raw[];

// =============================================================================
// BIG merged GEMM (single-sync multistage): job0 = V (fp16, bias bv),
// job1 = ah1 (f32, bias ba). BM2=256, BN=64, warp tile 64x32, K=1024.
// =============================================================================
__global__ __launch_bounds__(GT) void gemm_big(
    const __half* __restrict__ Av, const __half* __restrict__ Wv,
    const float* __restrict__ bv, __half* __restrict__ Vout,
    const __half* __restrict__ Aa, const __half* __restrict__ Wa,
    const float* __restrict__ ba, float* __restrict__ ah1,
    int nblk0)
{
    const int tid  = threadIdx.x;
    const int lane = tid & 31;
    const int warp = tid >> 5;
    const int wm   = warp & 3;
    const int wn   = warp >> 2;
    const int bid  = blockIdx.x;

    const bool jobV = bid < nblk0;
    const __half* A; const __half* W; int m0, n0, Ntot;
    if (jobV) { A = Av; W = Wv; n0 = (bid % 7) * BN; m0 = (bid / 7) * BM2; Ntot = NBIG; }
    else      { A = Aa; W = Wa; n0 = (bid - nblk0) * BN; m0 = 0;           Ntot = ATT_; }

    const uint32_t sbase = smem_u32(smem_raw);
    const int K = RNN_;
    const int ktotal = K / 64;   // 16

    auto load_stage = [&](int l) {
        const int s  = l % STAGES;
        const int kk = l * 64;
        const uint32_t abase = sbase + s * STAGE_BYTES2;
        const uint32_t bbase = abase + A_STAGE2;
        #pragma unroll
        for (int i = 0; i < 8; i++) {
            int q = tid + i * GT;
            int row = q >> 3, c = q & 7;
            cp16(abase + row * 128 + ((c ^ (row & 7)) << 4),
                 A + (size_t)(m0 + row) * K + kk + c * 8);
        }
        #pragma unroll
        for (int i = 0; i < 2; i++) {
            int q = tid + i * GT;
            int row = q >> 3, c = q & 7;
            int gr = n0 + row;
            const __half* src; int sz;
            if (gr < Ntot) { src = W + (size_t)gr * K + kk + c * 8; sz = 16; }
            else           { src = W;                               sz = 0;  }
            cp16z(bbase + row * 128 + ((c ^ (row & 7)) << 4), src, sz);
        }
        asm volatile("cp.async.commit_group;" ::: "memory");
    };

    float acc[4][4][4] = {};
    const int laneRow = lane & 7;
    const int m8      = (lane >> 3) & 1;
    const int cAdd    = lane >> 4;
    uint32_t aOff[4];
    #pragma unroll
    for (int f = 0; f < 4; f++)
        aOff[f] = (uint32_t)(wm * 64 + f * 16 + m8 * 8 + laneRow) * 128;
    const uint32_t bOff = (uint32_t)(wn * 32 + (lane >> 3) * 8 + laneRow) * 128;

    load_stage(0);
    load_stage(1);

    for (int kt = 0; kt < ktotal; ++kt) {
        asm volatile("cp.async.wait_group 1;" ::: "memory");
        __syncthreads();
        if (kt + 2 < ktotal) load_stage(kt + 2);
        else asm volatile("cp.async.commit_group;" ::: "memory");

        const uint32_t abase = sbase + (kt % STAGES) * STAGE_BYTES2;
        const uint32_t bbase = abase + A_STAGE2;
        #pragma unroll
        for (int ks = 0; ks < 4; ++ks) {
            uint32_t a[4][4], b0[4], b1[4];
            uint32_t aSw = (uint32_t)(((2 * ks + cAdd) ^ laneRow) << 4);
            LDSM4(b0, bbase + bOff + (uint32_t)(((2 * ks)     ^ laneRow) << 4));
            LDSM4(b1, bbase + bOff + (uint32_t)(((2 * ks + 1) ^ laneRow) << 4));
            #pragma unroll
            for (int f = 0; f < 4; f++) LDSM4(a[f], abase + aOff[f] + aSw);
            #pragma unroll
            for (int f = 0; f < 4; f++)
                #pragma unroll
                for (int j = 0; j < 4; j++)
                    MMA16816(acc[f][j], a[f], b0[j], b1[j]);
        }
    }
    __syncthreads();   // all warps done reading stages before Cst alias

    float* Cst = (float*)smem_raw;
    #pragma unroll
    for (int f = 0; f < 4; f++)
        #pragma unroll
        for (int j = 0; j < 4; j++) {
            int r0 = wm * 64 + f * 16 + (lane >> 2);
            int c0 = wn * 32 + j * 8 + (lane & 3) * 2;
            Cst[r0 * CLD + c0]           = acc[f][j][0];
            Cst[r0 * CLD + c0 + 1]       = acc[f][j][1];
            Cst[(r0 + 8) * CLD + c0]     = acc[f][j][2];
            Cst[(r0 + 8) * CLD + c0 + 1] = acc[f][j][3];
        }
    __syncthreads();

    for (int idx = tid; idx < BM2 * BN; idx += GT) {
        int r = idx >> 6, c = idx & 63, gc = n0 + c;
        if (gc < Ntot) {
            float v = Cst[r * CLD + c];
            if (jobV) Vout[(size_t)(m0 + r) * NBIG + gc] = __float2half(v + bv[gc]);
            else      ah1[(size_t)(m0 + r) * ATT_ + gc]  = v + ba[gc];
        }
    }
}

// =============================================================================
// small split-K GEMM with red.add epilogue (output pre-initialized with bias).
// =============================================================================
__global__ __launch_bounds__(GT) void gemm_red(
    const __half* __restrict__ A0, const __half* __restrict__ A1,
    const __half* __restrict__ A2,
    const __half* __restrict__ W0, const __half* __restrict__ W1,
    const __half* __restrict__ W2,
    float* __restrict__ Cf, int ldc, int Ntot, int Kld, int Kchunk,
    int kofs_per_z)
{
    const int tid  = threadIdx.x;
    const int lane = tid & 31;
    const int warp = tid >> 5;
    const int wm   = warp & 3;
    const int wn   = warp >> 2;
    const int n0   = blockIdx.x * BN;
    const int m0   = blockIdx.y * BM;
    const int z    = blockIdx.z;

    const __half* A; const __half* W; int kofs;
    if (kofs_per_z) { A = A0; W = W0; kofs = z * kofs_per_z; }
    else {
        A = (z == 0) ? A0 : (z == 1) ? A1 : A2;
        W = (z == 0) ? W0 : (z == 1) ? W1 : W2;
        kofs = 0;
    }

    const uint32_t sbase = smem_u32(smem_raw);
    const int ktotal = Kchunk / 64;

    auto load_stage = [&](int l) {
        const int s  = l % STAGES;
        const int kk = kofs + l * 64;
        const uint32_t abase = sbase + s * STAGE_BYTES;
        const uint32_t bbase = abase + A_STAGE;
        #pragma unroll
        for (int i = 0; i < 4; i++) {
            int q = tid + i * GT;
            int row = q >> 3, c = q & 7;
            cp16(abase + row * 128 + ((c ^ (row & 7)) << 4),
                 A + (size_t)(m0 + row) * Kld + kk + c * 8);
        }
        #pragma unroll
        for (int i = 0; i < 2; i++) {
            int q = tid + i * GT;
            int row = q >> 3, c = q & 7;
            int gr = n0 + row;
            const __half* src; int sz;
            if (gr < Ntot) { src = W + (size_t)gr * Kld + kk + c * 8; sz = 16; }
            else           { src = W;                                  sz = 0;  }
            cp16z(bbase + row * 128 + ((c ^ (row & 7)) << 4), src, sz);
        }
        asm volatile("cp.async.commit_group;" ::: "memory");
    };

    float acc[2][4][4] = {};
    const int laneRow = lane & 7;
    const int m8      = (lane >> 3) & 1;
    const int cAdd    = lane >> 4;
    const uint32_t aOff0 = (uint32_t)(wm * 32 + m8 * 8 + laneRow) * 128;
    const uint32_t aOff1 = aOff0 + 16 * 128;
    const uint32_t bOff  = (uint32_t)(wn * 32 + (lane >> 3) * 8 + laneRow) * 128;

    load_stage(0);
    load_stage(1);

    for (int kt = 0; kt < ktotal; ++kt) {
        asm volatile("cp.async.wait_group 1;" ::: "memory");
        __syncthreads();
        if (kt + 2 < ktotal) load_stage(kt + 2);
        else asm volatile("cp.async.commit_group;" ::: "memory");

        const uint32_t abase = sbase + (kt % STAGES) * STAGE_BYTES;
        const uint32_t bbase = abase + A_STAGE;
        #pragma unroll
        for (int ks = 0; ks < 4; ++ks) {
            uint32_t a[2][4], b0[4], b1[4];
            uint32_t aSw = (uint32_t)(((2 * ks + cAdd) ^ laneRow) << 4);
            LDSM4(a[0], abase + aOff0 + aSw);
            LDSM4(a[1], abase + aOff1 + aSw);
            LDSM4(b0, bbase + bOff + (uint32_t)(((2 * ks)     ^ laneRow) << 4));
            LDSM4(b1, bbase + bOff + (uint32_t)(((2 * ks + 1) ^ laneRow) << 4));
            #pragma unroll
            for (int f = 0; f < 2; f++)
                #pragma unroll
                for (int j = 0; j < 4; j++)
                    MMA16816(acc[f][j], a[f], b0[j], b1[j]);
        }
    }
    __syncthreads();

    float* Cst = (float*)smem_raw;
    #pragma unroll
    for (int f = 0; f < 2; f++)
        #pragma unroll
        for (int j = 0; j < 4; j++) {
            int r0 = wm * 32 + f * 16 + (lane >> 2);
            int c0 = wn * 32 + j * 8 + (lane & 3) * 2;
            Cst[r0 * CLD + c0]           = acc[f][j][0];
            Cst[r0 * CLD + c0 + 1]       = acc[f][j][1];
            Cst[(r0 + 8) * CLD + c0]     = acc[f][j][2];
            Cst[(r0 + 8) * CLD + c0 + 1] = acc[f][j][3];
        }
    __syncthreads();

    for (int idx = tid; idx < BM * BN; idx += GT) {
        int r = idx >> 6, c = idx & 63, gc = n0 + c;
        if (gc < Ntot)
            red_add(Cf + (size_t)(m0 + r) * ldc + gc, Cst[r * CLD + c]);
    }
}

// ---------------- mega convert -------------------------------------------------
__global__ __launch_bounds__(256) void convert_all(
    const float* __restrict__ att, const float* __restrict__ x,
    const float* __restrict__ ph,
    const float* __restrict__ wa2a, const float* __restrict__ wa2a1,
    const float* __restrict__ wh2a, const float* __restrict__ wh2a1,
    const float* __restrict__ wi,   const float* __restrict__ wh,
    const float* __restrict__ wa,   __half* __restrict__ buf)
{
    const size_t e0 = SZ_ATT / 4;
    const size_t e1 = e0 + SZ_BV / 4;
    const size_t e2 = e1 + SZ_BV / 4;
    const size_t e3 = e2 + SZ_WATT / 4;
    const size_t e4 = e3 + SZ_WATT / 4;
    const size_t e5 = e4 + SZ_WATT / 4;
    const size_t e6 = e5 + SZ_WATT / 4;
    const size_t e7 = e6 + SZ_WL / 4;
    const size_t e8 = e7 + SZ_WL / 4;
    const size_t e9 = e8 + SZ_WL / 4;

    size_t i = (size_t)blockIdx.x * blockDim.x + threadIdx.x;
    if (i >= e9) return;

    const float* src; size_t rel; size_t dofs;
    if      (i < e0) { src = att;   rel = i;      dofs = OFF_ATT; }
    else if (i < e1) { src = x;     rel = i - e0; dofs = OFF_X; }
    else if (i < e2) { src = ph;    rel = i - e1; dofs = OFF_PH; }
    else if (i < e3) { src = wa2a;  rel = i - e2; dofs = OFF_WBIG; }
    else if (i < e4) { src = wa2a1; rel = i - e3; dofs = OFF_WBIG + SZ_WATT; }
    else if (i < e5) { src = wh2a;  rel = i - e4; dofs = OFF_WH2A; }
    else if (i < e6) { src = wh2a1; rel = i - e5; dofs = OFF_WH2A1; }
    else if (i < e7) { src = wi;    rel = i - e6; dofs = OFF_WI2H; }
    else if (i < e8) { src = wh;    rel = i - e7; dofs = OFF_WH2H; }
    else             { src = wa;    rel = i - e8; dofs = OFF_WA2H; }

    float4 v = ((const float4*)src)[rel];
    __half2 h0 = __floats2half2_rn(v.x, v.y);
    __half2 h1 = __floats2half2_rn(v.z, v.w);
    ((__half2*)(buf + dofs))[2 * rel]     = h0;
    ((__half2*)(buf + dofs))[2 * rel + 1] = h1;
}

// ---------------- prep: bbig, S := fused lstm bias, ah2 := bias ---------------
__global__ __launch_bounds__(256) void prep_kernel(
    const float* __restrict__ ba,  const float* __restrict__ ba1,
    const float* __restrict__ bi,  const float* __restrict__ bh,
    const float* __restrict__ bg,  const float* __restrict__ bh2a1,
    float* __restrict__ bbig, float* __restrict__ S, float* __restrict__ ah2)
{
    size_t i = (size_t)blockIdx.x * blockDim.x + threadIdx.x;
    if (i < NBIG) bbig[i] = (i < ATT_) ? ba[i] : ba1[i - ATT_];
    if (i < (size_t)B_ * ATT_) {
        int a = (int)(i - (i / ATT_) * ATT_);
        ah2[i] = bh2a1[a];
    }
    if (i < (size_t)B_ * 4 * RNN_) {
        int j = (int)(i & (4 * RNN_ - 1));
        S[i] = bi[j] + bh[j] + bg[j];
    }
}

// ---------------- dot[m] = bd + sum_j Wd[j]*tanh(V[m,j] + ah[m]) --------------
__global__ __launch_bounds__(256) void reduce_dot_kernel(
    const __half* __restrict__ V, int colofs, const float* __restrict__ ah,
    const float* __restrict__ Wd, const float* __restrict__ bd,
    float* __restrict__ dotv, int Mrows)
{
    int m    = (blockIdx.x * blockDim.x + threadIdx.x) >> 5;
    int lane = threadIdx.x & 31;
    if (m >= Mrows) return;
    float ahm = ah[m];
    const __half2* vr2 = (const __half2*)(V + (size_t)m * NBIG + colofs);
    const float2*  wd2 = (const float2*)Wd;
    float s = 0.f;
    #pragma unroll 2
    for (int j = lane; j < ATT_ / 2; j += 32) {
        float2 f = __half22float2(vr2[j]);
        float2 w = wd2[j];
        s += w.x * tanh_s(f.x + ahm) + w.y * tanh_s(f.y + ahm);
    }
    #pragma unroll
    for (int o = 16; o; o >>= 1) s += __shfl_down_sync(0xffffffffu, s, o);
    if (lane == 0) dotv[m] = s + bd[0];
}

// ---------------- softmax over ATT per batch row -------------------------------
__global__ __launch_bounds__(256) void softmax_kernel(
    const float* __restrict__ dotv, float* __restrict__ w)
{
    int b = blockIdx.x;
    int t = threadIdx.x;
    __shared__ float sd[256];
    float v = (t < ATT_) ? dotv[b * ATT_ + t] : -1e30f;
    sd[t] = v; __syncthreads();
    #pragma unroll
    for (int s = 128; s; s >>= 1) { if (t < s) sd[t] = fmaxf(sd[t], sd[t + s]); __syncthreads(); }
    float mx = sd[0]; __syncthreads();
    float e = (t < ATT_) ? expf(v - mx) : 0.f;
    sd[t] = e; __syncthreads();
    #pragma unroll
    for (int s = 128; s; s >>= 1) { if (t < s) sd[t] += sd[t + s]; __syncthreads(); }
    float inv = 1.0f / sd[0];
    if (t < ATT_) w[b * ATT_ + t] = e * inv;
}

// ---------------- attres --------------------------------------------------------
__global__ __launch_bounds__(128) void attres_kernel(
    const __half* __restrict__ attH, const float* __restrict__ w,
    const float* __restrict__ addend, float* __restrict__ outF,
    __half* __restrict__ outH)
{
    int b = blockIdx.x;
    int t = threadIdx.x;
    __shared__ float ws[ATT_];
    for (int a = t; a < ATT_; a += 128) ws[a] = w[b * ATT_ + a];
    __syncthreads();
    int col = t * 8;
    const uint4* base = (const uint4*)(attH + (size_t)b * ATT_ * RNN_ + col);
    float s[8] = {};
    #pragma unroll 4
    for (int a = 0; a < ATT_; ++a) {
        uint4 u = base[(size_t)a * (RNN_ / 8)];
        const __half2* hp = (const __half2*)&u;
        float wa = ws[a];
        #pragma unroll
        for (int q = 0; q < 4; q++) {
            float2 f = __half22float2(hp[q]);
            s[2 * q]     += wa * f.x;
            s[2 * q + 1] += wa * f.y;
        }
    }
    if (addend) {
        #pragma unroll
        for (int q = 0; q < 8; q++) s[q] += addend[(size_t)b * RNN_ + col + q];
    }
    if (outF) {
        #pragma unroll
        for (int q = 0; q < 8; q += 4)
            *(float4*)(outF + (size_t)b * RNN_ + col + q) =
                make_float4(s[q], s[q + 1], s[q + 2], s[q + 3]);
    }
    if (outH) {
        __half2 h[4];
        #pragma unroll
        for (int q = 0; q < 4; q++) h[q] = __floats2half2_rn(s[2 * q], s[2 * q + 1]);
        *(uint4*)(outH + (size_t)b * RNN_ + col) = *(uint4*)h;
    }
}

// ---------------- LSTM gates ----------------------------------------------------
__global__ __launch_bounds__(256) void gates_kernel(
    const float* __restrict__ S, const float* __restrict__ prev_c,
    float* __restrict__ next_c, float* __restrict__ next_h,
    __half* __restrict__ nhH)
{
    int i = blockIdx.x * blockDim.x + threadIdx.x;
    int b = i >> 10, n = i & 1023;
    const float* s = S + (size_t)b * 4 * RNN_;
    float si = s[n];
    float sf = s[RNN_ + n];
    float so = s[2 * RNN_ + n];
    float st = s[3 * RNN_ + n];
    float c = sigmoid_s(sf) * prev_c[i] + sigmoid_s(si) * tanh_s(st);
    float h = sigmoid_s(so) * tanh_s(c);
    next_c[i] = c;
    next_h[i] = h;
    nhH[i]    = __float2half(h);
}

// ---------------- launcher ------------------------------------------------------
extern "C" void kernel_launch(void* const* d_in, const int* in_sizes, int n_in,
                              void* d_out, int out_size)
{
    const float* x      = (const float*)d_in[0];
    const float* att    = (const float*)d_in[1];
    const float* prev_h = (const float*)d_in[2];
    const float* prev_c = (const float*)d_in[3];
    const float* W_a2a  = (const float*)d_in[4];
    const float* b_a2a  = (const float*)d_in[5];
    const float* W_h2a  = (const float*)d_in[6];
    const float* b_h2a  = (const float*)d_in[7];
    const float* W_d2d  = (const float*)d_in[8];
    const float* b_d2d  = (const float*)d_in[9];
    const float* W_a2h  = (const float*)d_in[10];
    const float* b_a2h  = (const float*)d_in[11];
    const float* W_i2h  = (const float*)d_in[12];
    const float* b_i2h  = (const float*)d_in[13];
    const float* W_h2h  = (const float*)d_in[14];
    const float* b_h2h  = (const float*)d_in[15];
    const float* W_a2a1 = (const float*)d_in[16];
    const float* b_a2a1 = (const float*)d_in[17];
    const float* W_h2a1 = (const float*)d_in[18];
    const float* b_h2a1 = (const float*)d_in[19];
    const float* W_d2d1 = (const float*)d_in[20];
    const float* b_d2d1 = (const float*)d_in[21];

    float* out    = (float*)d_out;
    float* next_c = out;
    float* next_h = out + (size_t)B_ * RNN_;
    float* top_h  = out + (size_t)2 * B_ * RNN_;

    __half* H; __half* V;
    float *bbig, *ah1, *ah2, *dotv, *w1, *w2, *S;
    cudaGetSymbolAddress((void**)&H,    g_h);
    cudaGetSymbolAddress((void**)&V,    g_V);
    cudaGetSymbolAddress((void**)&bbig, g_bbig);
    cudaGetSymbolAddress((void**)&ah1,  g_ah1);
    cudaGetSymbolAddress((void**)&ah2,  g_ah2);
    cudaGetSymbolAddress((void**)&dotv, g_dot);
    cudaGetSymbolAddress((void**)&w1,   g_w1);
    cudaGetSymbolAddress((void**)&w2,   g_w2);
    cudaGetSymbolAddress((void**)&S,    g_S);

    cudaFuncSetAttribute(gemm_red, cudaFuncAttributeMaxDynamicSharedMemorySize, GEMM_SMEM);
    cudaFuncSetAttribute(gemm_big, cudaFuncAttributeMaxDynamicSharedMemorySize, GEMM_SMEM2);

    const int Mbig = B_ * ATT_;                 // 50176
    const int NBLK0 = 7 * (Mbig / BM2);         // 1372
    const size_t CV_TOT = OFF_ARES1 / 4;

    // 1) prep (biases + S/ah2 init)
    prep_kernel<<<(unsigned)((B_ * 4 * RNN_ + 255) / 256), 256>>>(
        b_a2a, b_a2a1, b_i2h, b_h2h, b_a2h, b_h2a1, bbig, S, ah2);

    // 2) convert all f32 -> fp16 arena
    convert_all<<<(unsigned)((CV_TOT + 255) / 256), 256>>>(
        att, x, prev_h, W_a2a, W_a2a1, W_h2a, W_h2a1, W_i2h, W_h2h, W_a2h, H);

    // 3) merged: V = attH @ [Wa2a|Wa2a1]^T  +  ah1 = prev_h @ W_h2a^T
    gemm_big<<<NBLK0 + 4, GT, GEMM_SMEM2>>>(
        H + OFF_ATT, H + OFF_WBIG, bbig, V,
        H + OFF_PH,  H + OFF_WH2A, b_h2a, ah1, NBLK0);

    // 4) attend 1
    reduce_dot_kernel<<<Mbig / 8, 256>>>(V, 0, ah1, W_d2d, b_d2d, dotv, Mbig);
    softmax_kernel<<<B_, 256>>>(dotv, w1);
    attres_kernel<<<B_, 128>>>(H + OFF_ATT, w1, nullptr, nullptr, H + OFF_ARES1);

    // 5) LSTM: S += xH@Wi^T + phH@Wh^T + ares1H@Wa^T  (3-way split-K red.add)
    gemm_red<<<dim3(64, 2, 3), GT, GEMM_SMEM>>>(
        H + OFF_X, H + OFF_PH, H + OFF_ARES1,
        H + OFF_WI2H, H + OFF_WH2H, H + OFF_WA2H,
        S, 4 * RNN_, 4 * RNN_, RNN_, RNN_, 0);

    gates_kernel<<<(B_ * RNN_) / 256, 256>>>(S, prev_c, next_c, next_h, H + OFF_NH);

    // 6) ah2 += next_h @ W_h2a1^T  (4-way split-K red.add)
    gemm_red<<<dim3(4, 2, 4), GT, GEMM_SMEM>>>(
        H + OFF_NH, nullptr, nullptr, H + OFF_WH2A1, nullptr, nullptr,
        ah2, ATT_, ATT_, RNN_, RNN_ / 4, RNN_ / 4);

    // 7) attend 2
    reduce_dot_kernel<<<Mbig / 8, 256>>>(V, ATT_, ah2, W_d2d1, b_d2d1, dotv, Mbig);
    softmax_kernel<<<B_, 256>>>(dotv, w2);
    attres_kernel<<<B_, 128>>>(H + OFF_ATT, w2, next_h, top_h, nullptr);
}